// round 1
// baseline (speedup 1.0000x reference)
#include <cuda_runtime.h>
#include <math_constants.h>
#include <math.h>

#define BSZ 4
#define NP  2048
#define EPSF 1e-6f

// ---------------- scratch (no allocations allowed) ----------------
__device__ float g_knn[2][BSZ][NP * 3];     // sqrt'd 3-NN dists (incl self), real=0 fake=1
__device__ float g_sorted[14][8192];        // 0..5 channel sorts, 6..13 knn sorts
__device__ float g_hex_partial[1024];       // per-block sum of |psi|
__device__ float g_feas_partial[144];       // per-block overlap sums

// ---------------- warp helpers ----------------
__device__ __forceinline__ float warp_extract_min(float& a0, float& a1, float& a2, float& a3,
                                                  int lane, int kmax) {
    // pops the warp-global min from the (sorted) per-lane lists; kmax regs used
    float bv = a0; int bl = lane;
#pragma unroll
    for (int off = 16; off; off >>= 1) {
        float ov = __shfl_down_sync(0xffffffffu, bv, off);
        int   ol = __shfl_down_sync(0xffffffffu, bl, off);
        if (ov < bv) { bv = ov; bl = ol; }
    }
    bv = __shfl_sync(0xffffffffu, bv, 0);
    bl = __shfl_sync(0xffffffffu, bl, 0);
    if (lane == bl) {
        a0 = a1; a1 = a2;
        if (kmax > 3) { a2 = a3; a3 = CUDART_INF_F; }
        else          { a2 = CUDART_INF_F; }
    }
    return bv;
}

// ---------------- kNN (k=3, includes self-dist sqrt(EPS)) ----------------
__global__ void knn_kernel(const float* __restrict__ real_in, const float* __restrict__ fake_in) {
    __shared__ float2 sxy[NP];
    int bx = blockIdx.x;                  // 0..2047
    int t  = bx >> 10;                    // 0 real, 1 fake
    int b  = (bx >> 8) & 3;
    int i0 = (bx & 255) * 8;
    const float* base = (t ? fake_in : real_in) + b * NP * 3;
    for (int j = threadIdx.x; j < NP; j += blockDim.x)
        sxy[j] = make_float2(base[j * 3], base[j * 3 + 1]);
    __syncthreads();

    int warp = threadIdx.x >> 5, lane = threadIdx.x & 31;
    int i = i0 + warp;
    float xi = sxy[i].x, yi = sxy[i].y;
    float a0 = CUDART_INF_F, a1 = CUDART_INF_F, a2 = CUDART_INF_F, a3 = CUDART_INF_F;
    for (int j = lane; j < NP; j += 32) {
        float dx = xi - sxy[j].x;
        float dy = yi - sxy[j].y;
        float d2 = fmaf(dx, dx, fmaf(dy, dy, EPSF));
        if (d2 < a2) {
            if (d2 < a1) { a2 = a1; if (d2 < a0) { a1 = a0; a0 = d2; } else a1 = d2; }
            else a2 = d2;
        }
    }
    float o0 = warp_extract_min(a0, a1, a2, a3, lane, 3);
    float o1 = warp_extract_min(a0, a1, a2, a3, lane, 3);
    float o2 = warp_extract_min(a0, a1, a2, a3, lane, 3);
    if (lane == 0) {
        float* dst = &g_knn[t][b][i * 3];
        dst[0] = sqrtf(o0); dst[1] = sqrtf(o1); dst[2] = sqrtf(o2);
    }
}

// ---------------- hexatic order (k=4) on fake ----------------
__global__ void hex_kernel(const float* __restrict__ fake_in) {
    __shared__ float2 sxy[NP];
    __shared__ float s_acc[8];
    int bx = blockIdx.x;                  // 0..1023
    int b  = bx >> 8;
    int i0 = (bx & 255) * 8;
    const float* base = fake_in + b * NP * 3;
    for (int j = threadIdx.x; j < NP; j += blockDim.x)
        sxy[j] = make_float2(base[j * 3], base[j * 3 + 1]);
    __syncthreads();

    int warp = threadIdx.x >> 5, lane = threadIdx.x & 31;
    int i = i0 + warp;
    float xi = sxy[i].x, yi = sxy[i].y;

    // pass 1: 4 smallest squared dists (excluding self)
    float a0 = CUDART_INF_F, a1 = CUDART_INF_F, a2 = CUDART_INF_F, a3 = CUDART_INF_F;
    for (int j = lane; j < NP; j += 32) {
        float dx = xi - sxy[j].x;
        float dy = yi - sxy[j].y;
        float d2 = fmaf(dx, dx, fmaf(dy, dy, EPSF));
        if (j == i) d2 = CUDART_INF_F;
        if (d2 < a3) {
            if (d2 < a1) {
                a3 = a2; a2 = a1;
                if (d2 < a0) { a1 = a0; a0 = d2; } else a1 = d2;
            } else {
                a3 = a2;
                if (d2 < a2) a2 = d2; else a3 = d2;
            }
        }
    }
    float kth2 = 0.0f;
#pragma unroll
    for (int r = 0; r < 4; r++)
        kth2 = warp_extract_min(a0, a1, a2, a3, lane, 4);
    float kth = sqrtf(kth2);
    float sigma = fmaxf(0.1f * fmaxf(kth, EPSF), EPSF);
    float inv_sigma = 1.0f / sigma;
    float lim = kth + 18.0f * sigma;      // beyond this, w <= sigmoid(-18) ~ 1.5e-8: negligible
    float lim2 = lim * lim;

    // pass 2: weighted orientation sums
    float wsum = 0.0f, wre = 0.0f, wim = 0.0f;
    for (int j = lane; j < NP; j += 32) {
        float dx = xi - sxy[j].x;
        float dy = yi - sxy[j].y;
        float d2 = fmaf(dx, dx, fmaf(dy, dy, EPSF));
        if (j != i && d2 <= lim2) {
            float dist = sqrtf(d2);
            float arg = (kth - dist) * inv_sigma;            // in [-18, ~10]
            float w = 1.0f / (1.0f + expf(-arg));
            float c = dx;
            if (fabsf(c) < EPSF) c = c + EPSF;               // ref: dx += EPS when |dx|<EPS
            float n2 = fmaf(c, c, dy * dy);
            float inv = 1.0f / n2;
            float un = (c * c - dy * dy) * inv;              // cos(2t)
            float vn = (2.0f * c * dy) * inv;                // sin(2t)
            float re4 = un * un - vn * vn;                   // cos(4t)
            float im4 = 2.0f * un * vn;                      // sin(4t)
            wsum += w;
            wre = fmaf(w, re4, wre);
            wim = fmaf(w, im4, wim);
        }
    }
#pragma unroll
    for (int off = 16; off; off >>= 1) {
        wsum += __shfl_down_sync(0xffffffffu, wsum, off);
        wre  += __shfl_down_sync(0xffffffffu, wre,  off);
        wim  += __shfl_down_sync(0xffffffffu, wim,  off);
    }
    if (lane == 0) {
        float denom = fmaxf(wsum, EPSF);
        s_acc[warp] = sqrtf(wre * wre + wim * wim) / denom;
    }
    __syncthreads();
    if (threadIdx.x == 0) {
        float s = 0.0f;
        for (int w = 0; w < 8; w++) s += s_acc[w];
        g_hex_partial[bx] = s;
    }
}

// ---------------- physical feasibility (fake), tiled lower-triangle ----------------
__global__ void feas_kernel(const float* __restrict__ fake_in) {
    __shared__ float sJx[256], sJy[256], sJr[256];
    __shared__ float red[256];
    int bx = blockIdx.x;                  // 0..143
    int b = bx / 36;
    int r = bx % 36;
    int ti = 0;
    while ((ti + 1) * (ti + 2) / 2 <= r) ti++;
    int tj = r - ti * (ti + 1) / 2;

    const float* base = fake_in + b * NP * 3;
    int t = threadIdx.x;
    {
        int gj = tj * 256 + t;
        sJx[t] = base[gj * 3];
        sJy[t] = base[gj * 3 + 1];
        sJr[t] = fabsf(base[gj * 3 + 2]);
    }
    __syncthreads();

    int gi = ti * 256 + t;
    float xi = base[gi * 3], yi = base[gi * 3 + 1], ri = fabsf(base[gi * 3 + 2]);
    float acc = 0.0f;
    int jmax = (ti == tj) ? t : 256;      // strict lower triangle (i > j)
    for (int j = 0; j < jmax; j++) {
        float dx = xi - sJx[j];
        float dy = yi - sJy[j];
        float sq = fmaf(dx, dx, dy * dy);
        float thr = ri + sJr[j] - 1e-4f;
        if (sq > 0.0f && thr > 0.0f && sq < thr * thr)
            acc += thr - sqrtf(sq);
    }
    red[t] = acc;
    __syncthreads();
    for (int off = 128; off; off >>= 1) {
        if (t < off) red[t] += red[t + off];
        __syncthreads();
    }
    if (t == 0) g_feas_partial[bx] = red[0];
}

// ---------------- bitonic sorts (14 arrays) ----------------
__global__ void sort_kernel(const float* __restrict__ real_in, const float* __restrict__ fake_in) {
    __shared__ float s[8192];
    int a = blockIdx.x;                   // 0..13
    int t = threadIdx.x;
    if (a < 6) {
        const float* src = (a < 3 ? real_in : fake_in);
        int c = a % 3;
        for (int i = t; i < 8192; i += 1024) s[i] = src[i * 3 + c];
    } else {
        int idx = a - 6;
        const float* src = &g_knn[idx >> 2][idx & 3][0];
        for (int i = t; i < 8192; i += 1024) s[i] = (i < NP * 3) ? src[i] : CUDART_INF_F;
    }
    __syncthreads();
    for (int k = 2; k <= 8192; k <<= 1) {
        for (int j = k >> 1; j > 0; j >>= 1) {
            for (int i = t; i < 8192; i += 1024) {
                int ix = i ^ j;
                if (ix > i) {
                    float u = s[i], v = s[ix];
                    bool up = ((i & k) == 0);
                    if ((u > v) == up) { s[i] = v; s[ix] = u; }
                }
            }
            __syncthreads();
        }
    }
    for (int i = t; i < 8192; i += 1024) g_sorted[a][i] = s[i];
}

// ---------------- finalize ----------------
__device__ __forceinline__ float quantile_dev(const float* a, int n, float q) {
    float pos = q * (float)(n - 1);
    int lo = (int)floorf(pos);
    if (lo > n - 2) lo = n - 2;
    float fr = pos - (float)lo;
    return a[lo] + fr * (a[lo + 1] - a[lo]);
}

__global__ void final_kernel(const float* __restrict__ fake_in,
                             const float* __restrict__ fo,
                             float* __restrict__ out) {
    __shared__ float red[1024];
    __shared__ float s_sumr, s_hex, s_feas;
    int t = threadIdx.x;

    // sum |r| over fake
    float s = 0.0f;
    for (int i = t; i < BSZ * NP; i += 1024) s += fabsf(fake_in[i * 3 + 2]);
    red[t] = s; __syncthreads();
    for (int off = 512; off; off >>= 1) { if (t < off) red[t] += red[t + off]; __syncthreads(); }
    if (t == 0) s_sumr = red[0];
    __syncthreads();

    // hexatic partial sum
    red[t] = g_hex_partial[t]; __syncthreads();
    for (int off = 512; off; off >>= 1) { if (t < off) red[t] += red[t + off]; __syncthreads(); }
    if (t == 0) s_hex = red[0];
    __syncthreads();

    // feasibility partial sum
    red[t] = (t < 144) ? g_feas_partial[t] : 0.0f; __syncthreads();
    for (int off = 512; off; off >>= 1) { if (t < off) red[t] += red[t + off]; __syncthreads(); }
    if (t == 0) s_feas = red[0];
    __syncthreads();

    if (t == 0) {
        const float q7[7] = {0.05f, 0.1f, 0.25f, 0.5f, 0.75f, 0.9f, 0.95f};
        const float q5[5] = {0.05f, 0.25f, 0.5f, 0.75f, 0.95f};
        const float q3[3] = {0.05f, 0.5f, 0.95f};
        float loss = 0.0f;

        // radius loss: z channels (real=2, fake=5)
        {
            float acc = 0.0f;
            for (int k = 0; k < 7; k++) {
                float d = quantile_dev(g_sorted[5], 8192, q7[k]) -
                          quantile_dev(g_sorted[2], 8192, q7[k]);
                acc += d * d;
            }
            loss += acc / 7.0f;
        }
        // grid density loss: x (0/3) and y (1/4)
        {
            float ax = 0.0f, ay = 0.0f;
            for (int k = 0; k < 5; k++) {
                float dx = quantile_dev(g_sorted[3], 8192, q5[k]) -
                           quantile_dev(g_sorted[0], 8192, q5[k]);
                float dy = quantile_dev(g_sorted[4], 8192, q5[k]) -
                           quantile_dev(g_sorted[1], 8192, q5[k]);
                ax += dx * dx; ay += dy * dy;
            }
            loss += 0.5f * (ax / 5.0f + ay / 5.0f);
        }
        // distance loss: per-batch knn quantiles (real at 6+b, fake at 10+b)
        {
            float acc = 0.0f;
            for (int b = 0; b < BSZ; b++) {
                for (int k = 0; k < 3; k++) {
                    float d = quantile_dev(g_sorted[10 + b], NP * 3, q3[k]) -
                              quantile_dev(g_sorted[6 + b],  NP * 3, q3[k]);
                    acc += d * d;
                }
            }
            loss += acc / 12.0f;
        }
        // grid order loss
        loss += -s_hex / (float)(BSZ * NP);
        // physical feasibility: overlap_sum / (N * sum|r|)
        loss += s_feas / ((float)NP * s_sumr);
        // gan loss
        {
            float g = 0.0f;
            for (int i = 0; i < BSZ; i++) {
                float p = fo[i];
                g += 0.9f * fmaxf(logf(p), -100.0f) + 0.1f * fmaxf(logf(1.0f - p), -100.0f);
            }
            loss += -g / (float)BSZ;
        }
        out[0] = loss;
    }
}

// ---------------- launch ----------------
extern "C" void kernel_launch(void* const* d_in, const int* in_sizes, int n_in,
                              void* d_out, int out_size) {
    const float* real_in = (const float*)d_in[0];
    const float* fake_in = (const float*)d_in[1];
    const float* fo      = (const float*)d_in[2];
    float* out = (float*)d_out;

    knn_kernel <<<2048, 256>>>(real_in, fake_in);
    hex_kernel <<<1024, 256>>>(fake_in);
    feas_kernel<<<144, 256>>>(fake_in);
    sort_kernel<<<14, 1024>>>(real_in, fake_in);
    final_kernel<<<1, 1024>>>(fake_in, fo, out);
}

// round 3
// speedup vs baseline: 1.3987x; 1.3987x over previous
#include <cuda_runtime.h>
#include <math_constants.h>
#include <math.h>

#define BSZ 4
#define NP  2048
#define EPSF 1e-6f
#define INF  CUDART_INF_F

// ---------------- scratch ----------------
__device__ float g_knn[2][BSZ][NP * 3];   // sqrt'd 3NN (incl self): real=0, fake=1
__device__ float g_sel[14][14];           // selected order statistics
__device__ float g_hex_partial[256];
__device__ float g_feas_partial[144];

// ---------------- packed f32x2 helpers ----------------
__device__ __forceinline__ unsigned long long pk(float a, float b) {
    unsigned long long r; asm("mov.b64 %0,{%1,%2};" : "=l"(r) : "f"(a), "f"(b)); return r;
}
__device__ __forceinline__ float2 upk(unsigned long long v) {
    float2 r; asm("mov.b64 {%0,%1},%2;" : "=f"(r.x), "=f"(r.y) : "l"(v)); return r;
}
// q holds (xi, yi); nj holds (-xj, -yj). Returns squared dist (no EPS); s = packed diff.
__device__ __forceinline__ float dist2s(unsigned long long q, unsigned long long nj,
                                        unsigned long long& s) {
    asm("add.rn.f32x2 %0,%1,%2;" : "=l"(s) : "l"(q), "l"(nj));
    unsigned long long m;
    asm("mul.rn.f32x2 %0,%1,%2;" : "=l"(m) : "l"(s), "l"(s));
    float2 f = upk(m);
    return f.x + f.y;
}
__device__ __forceinline__ float dist2q(unsigned long long q, unsigned long long nj) {
    unsigned long long s; return dist2s(q, nj, s);
}

// ---------------- sorted-insert macros ----------------
#define INS3(a0,a1,a2,d) do{ \
    if ((d) < a2){ \
        if ((d) < a1){ a2=a1; if ((d) < a0){ a1=a0; a0=(d); } else a1=(d); } \
        else a2=(d); } }while(0)

#define INS5(a0,a1,a2,a3,a4,d) do{ \
    if ((d) < a4){ \
        if ((d) < a2){ \
            a4=a3; a3=a2; \
            if ((d) < a1){ a2=a1; if ((d) < a0){ a1=a0; a0=(d); } else a1=(d); } \
            else a2=(d); \
        } else { \
            if ((d) < a3){ a4=a3; a3=(d); } else a4=(d); } \
    } }while(0)

// ---------------- warp k-min extraction ----------------
__device__ __forceinline__ float pop3(float& a0, float& a1, float& a2, int lane) {
    float bv = a0; int bl = lane;
#pragma unroll
    for (int off = 16; off; off >>= 1) {
        float ov = __shfl_down_sync(0xffffffffu, bv, off);
        int   ol = __shfl_down_sync(0xffffffffu, bl, off);
        if (ov < bv) { bv = ov; bl = ol; }
    }
    bv = __shfl_sync(0xffffffffu, bv, 0);
    bl = __shfl_sync(0xffffffffu, bl, 0);
    if (lane == bl) { a0 = a1; a1 = a2; a2 = INF; }
    return bv;
}
__device__ __forceinline__ float pop5(float& a0, float& a1, float& a2, float& a3, float& a4,
                                      int lane) {
    float bv = a0; int bl = lane;
#pragma unroll
    for (int off = 16; off; off >>= 1) {
        float ov = __shfl_down_sync(0xffffffffu, bv, off);
        int   ol = __shfl_down_sync(0xffffffffu, bl, off);
        if (ov < bv) { bv = ov; bl = ol; }
    }
    bv = __shfl_sync(0xffffffffu, bv, 0);
    bl = __shfl_sync(0xffffffffu, bl, 0);
    if (lane == bl) { a0 = a1; a1 = a2; a2 = a3; a3 = a4; a4 = INF; }
    return bv;
}

// ---------------- real kNN: top-3 incl self (self d2 = 0 exactly), 4 pts/warp -------
__global__ void knn_kernel(const float* __restrict__ real_in) {
    __shared__ unsigned long long sneg[NP];
    int bx = blockIdx.x;                  // 256 blocks: 4 batches x 64
    int b  = bx >> 6;
    int ibase = (bx & 63) * 32;
    const float* base = real_in + b * NP * 3;
    for (int j = threadIdx.x; j < NP; j += 256)
        sneg[j] = pk(-base[j * 3], -base[j * 3 + 1]);
    __syncthreads();
    int warp = threadIdx.x >> 5, lane = threadIdx.x & 31;
    unsigned long long q[4];
    float acc[4][3];
#pragma unroll
    for (int p = 0; p < 4; p++) {
        float2 pp = upk(sneg[ibase + warp * 4 + p]);
        q[p] = pk(-pp.x, -pp.y);
        acc[p][0] = INF; acc[p][1] = INF; acc[p][2] = INF;
    }
    for (int j = lane; j < NP; j += 32) {
        unsigned long long nj = sneg[j];
#pragma unroll
        for (int p = 0; p < 4; p++) {
            float d = dist2q(q[p], nj);
            INS3(acc[p][0], acc[p][1], acc[p][2], d);
        }
    }
#pragma unroll
    for (int p = 0; p < 4; p++) {
        float o0 = pop3(acc[p][0], acc[p][1], acc[p][2], lane);
        float o1 = pop3(acc[p][0], acc[p][1], acc[p][2], lane);
        float o2 = pop3(acc[p][0], acc[p][1], acc[p][2], lane);
        if (lane == 0) {
            float* dst = &g_knn[0][b][(ibase + warp * 4 + p) * 3];
            dst[0] = sqrtf(o0 + EPSF); dst[1] = sqrtf(o1 + EPSF); dst[2] = sqrtf(o2 + EPSF);
        }
    }
}

// ---------------- hex contribution (shared by loop + self-subtraction) ----------------
__device__ __forceinline__ void hex_contrib(float dx, float dy, float d2,
                                            float kth, float inv_sigma,
                                            float& wsum, float& wre, float& wim) {
    float dist = sqrtf(d2 + EPSF);
    float arg = (kth - dist) * inv_sigma;              // gate guarantees arg in (-18, ~10)
    float e = __expf(-arg);
    float w = __fdividef(1.0f, 1.0f + e);
    float c = dx;
    if (fabsf(c) < EPSF) c = c + EPSF;
    float n2 = fmaf(c, c, dy * dy);
    float inv = __fdividef(1.0f, n2);
    float un = (c * c - dy * dy) * inv;                // cos 2t
    float vn = (2.0f * c * dy) * inv;                  // sin 2t
    float re4 = un * un - vn * vn;                     // cos 4t
    float im4 = 2.0f * un * vn;                        // sin 4t
    wsum += w;
    wre = fmaf(w, re4, wre);
    wim = fmaf(w, im4, wim);
}

// ---------------- fake: fused kNN + hexatic order, 4 pts/warp ----------------
__global__ void hex_kernel(const float* __restrict__ fake_in) {
    __shared__ unsigned long long sneg[NP];
    __shared__ float s_acc[8];
    int bx = blockIdx.x;                  // 256 blocks
    int b  = bx >> 6;
    int ibase = (bx & 63) * 32;
    const float* base = fake_in + b * NP * 3;
    for (int j = threadIdx.x; j < NP; j += 256)
        sneg[j] = pk(-base[j * 3], -base[j * 3 + 1]);
    __syncthreads();
    int warp = threadIdx.x >> 5, lane = threadIdx.x & 31;
    unsigned long long q[4];
    float acc[4][5];
#pragma unroll
    for (int p = 0; p < 4; p++) {
        float2 pp = upk(sneg[ibase + warp * 4 + p]);
        q[p] = pk(-pp.x, -pp.y);
        acc[p][0] = INF; acc[p][1] = INF; acc[p][2] = INF; acc[p][3] = INF; acc[p][4] = INF;
    }

    // pass 1: top-5 including self (self contributes exact 0)
    for (int j = lane; j < NP; j += 32) {
        unsigned long long nj = sneg[j];
#pragma unroll
        for (int p = 0; p < 4; p++) {
            float d = dist2q(q[p], nj);
            INS5(acc[p][0], acc[p][1], acc[p][2], acc[p][3], acc[p][4], d);
        }
    }
    float kth[4], isg[4], lim2[4];
#pragma unroll
    for (int p = 0; p < 4; p++) {
        float o0 = pop5(acc[p][0], acc[p][1], acc[p][2], acc[p][3], acc[p][4], lane);
        float o1 = pop5(acc[p][0], acc[p][1], acc[p][2], acc[p][3], acc[p][4], lane);
        float o2 = pop5(acc[p][0], acc[p][1], acc[p][2], acc[p][3], acc[p][4], lane);
        float o3 = pop5(acc[p][0], acc[p][1], acc[p][2], acc[p][3], acc[p][4], lane); (void)o3;
        float o4 = pop5(acc[p][0], acc[p][1], acc[p][2], acc[p][3], acc[p][4], lane);
        if (lane == 0) {   // kNN (incl self): o0 = 0(self), o1, o2
            float* dst = &g_knn[1][b][(ibase + warp * 4 + p) * 3];
            dst[0] = sqrtf(o0 + EPSF); dst[1] = sqrtf(o1 + EPSF); dst[2] = sqrtf(o2 + EPSF);
        }
        float kv = sqrtf(o4 + EPSF);   // 4th non-self neighbor distance
        float sg = fmaxf(0.1f * fmaxf(kv, EPSF), EPSF);
        kth[p] = kv;
        isg[p] = __fdividef(1.0f, sg);
        float lim = kv + 18.0f * sg;   // beyond: w <= sigmoid(-18) ~ 1.5e-8, negligible
        lim2[p] = fmaf(lim, lim, -EPSF);
    }

    // pass 2: weighted orientation sums (self passes gate; subtracted on lane 0 after)
    float ws[4] = {0.f, 0.f, 0.f, 0.f};
    float wr[4] = {0.f, 0.f, 0.f, 0.f};
    float wi[4] = {0.f, 0.f, 0.f, 0.f};
    for (int j = lane; j < NP; j += 32) {
        unsigned long long nj = sneg[j];
#pragma unroll
        for (int p = 0; p < 4; p++) {
            unsigned long long s;
            float d2 = dist2s(q[p], nj, s);
            if (d2 <= lim2[p]) {
                float2 dv = upk(s);
                hex_contrib(dv.x, dv.y, d2, kth[p], isg[p], ws[p], wr[p], wi[p]);
            }
        }
    }
#pragma unroll
    for (int p = 0; p < 4; p++) {
#pragma unroll
        for (int off = 16; off; off >>= 1) {
            ws[p] += __shfl_down_sync(0xffffffffu, ws[p], off);
            wr[p] += __shfl_down_sync(0xffffffffu, wr[p], off);
            wi[p] += __shfl_down_sync(0xffffffffu, wi[p], off);
        }
    }
    if (lane == 0) {
        float psum = 0.0f;
#pragma unroll
        for (int p = 0; p < 4; p++) {
            // subtract self contribution ONCE (exact same fp path as the loop's self term)
            float ss = 0.0f, sr = 0.0f, si = 0.0f;
            hex_contrib(0.0f, 0.0f, 0.0f, kth[p], isg[p], ss, sr, si);
            float wsum = ws[p] - ss;
            float wre  = wr[p] - sr;
            float wim  = wi[p] - si;
            psum += sqrtf(wre * wre + wim * wim) / fmaxf(wsum, EPSF);
        }
        s_acc[warp] = psum;
    }
    __syncthreads();
    if (threadIdx.x == 0) {
        float s = 0.0f;
        for (int w = 0; w < 8; w++) s += s_acc[w];
        g_hex_partial[bx] = s;
    }
}

// ---------------- physical feasibility (fake), tiled lower-triangle ----------------
__global__ void feas_kernel(const float* __restrict__ fake_in) {
    __shared__ float sJx[256], sJy[256], sJr[256];
    __shared__ float red[256];
    int bx = blockIdx.x;                  // 0..143
    int b = bx / 36;
    int r = bx % 36;
    int ti = 0;
    while ((ti + 1) * (ti + 2) / 2 <= r) ti++;
    int tj = r - ti * (ti + 1) / 2;

    const float* base = fake_in + b * NP * 3;
    int t = threadIdx.x;
    {
        int gj = tj * 256 + t;
        sJx[t] = base[gj * 3];
        sJy[t] = base[gj * 3 + 1];
        sJr[t] = fabsf(base[gj * 3 + 2]);
    }
    __syncthreads();

    int gi = ti * 256 + t;
    float xi = base[gi * 3], yi = base[gi * 3 + 1], ri = fabsf(base[gi * 3 + 2]);
    float acc = 0.0f;
    int jmax = (ti == tj) ? t : 256;      // strict lower triangle (i > j)
    for (int j = 0; j < jmax; j++) {
        float dx = xi - sJx[j];
        float dy = yi - sJy[j];
        float sq = fmaf(dx, dx, dy * dy);
        float thr = ri + sJr[j] - 1e-4f;
        if (sq > 0.0f && thr > 0.0f && sq < thr * thr)
            acc += thr - sqrtf(sq);
    }
    red[t] = acc;
    __syncthreads();
    for (int off = 128; off; off >>= 1) {
        if (t < off) red[t] += red[t + off];
        __syncthreads();
    }
    if (t == 0) g_feas_partial[bx] = red[0];
}

// ---------------- radix select: one block per (array, rank) ----------------
#define XY10 409,410,2047,2048,4095,4096,6143,6144,7781,7782
#define Z14  409,410,819,820,2047,2048,4095,4096,6143,6144,7371,7372,7781,7782
#define K6   307,308,3071,3072,5835,5836
#define R10(x) x,x,x,x,x,x,x,x,x,x
#define R14(x) x,x,x,x,x,x,x,x,x,x,x,x,x,x
#define R6(x)  x,x,x,x,x,x
#define S10 0,1,2,3,4,5,6,7,8,9
#define S14 0,1,2,3,4,5,6,7,8,9,10,11,12,13
#define S6  0,1,2,3,4,5

__constant__ unsigned short c_arr[116] = {
    R10(0), R10(1), R14(2), R10(3), R10(4), R14(5),
    R6(6), R6(7), R6(8), R6(9), R6(10), R6(11), R6(12), R6(13) };
__constant__ unsigned short c_rank[116] = {
    XY10, XY10, Z14, XY10, XY10, Z14, K6, K6, K6, K6, K6, K6, K6, K6 };
__constant__ unsigned char c_slot[116] = {
    S10, S10, S14, S10, S10, S14, S6, S6, S6, S6, S6, S6, S6, S6 };

__device__ __forceinline__ unsigned fkey(float f) {
    unsigned u = __float_as_uint(f);
    return (u & 0x80000000u) ? ~u : (u | 0x80000000u);
}

__global__ void select_kernel(const float* __restrict__ real_in,
                              const float* __restrict__ fake_in) {
    __shared__ int hist[2048];
    __shared__ int wtot[8], woff[8];
    __shared__ unsigned s_bin;
    __shared__ int s_rank;
    int task = blockIdx.x;
    int a = c_arr[task];
    int r = c_rank[task];
    const float* src; int n, stride;
    if (a < 6) { src = (a < 3 ? real_in : fake_in) + (a % 3); n = 8192; stride = 3; }
    else       { src = &g_knn[0][0][0] + (a - 6) * (NP * 3); n = NP * 3; stride = 1; }

    int tid = threadIdx.x, lane = tid & 31, wid = tid >> 5;
    unsigned prefix = 0;
#pragma unroll
    for (int level = 0; level < 3; level++) {
        int nb = (level < 2) ? 2048 : 1024;
        int shift = (level == 0) ? 21 : (level == 1 ? 10 : 0);
        for (int bI = tid; bI < nb; bI += 256) hist[bI] = 0;
        __syncthreads();
        for (int idx = tid; idx < n; idx += 256) {
            unsigned k = fkey(src[idx * stride]);
            bool ok = (level == 0) ||
                      (level == 1 ? ((k >> 21) == prefix) : ((k >> 10) == prefix));
            if (ok) atomicAdd(&hist[(k >> shift) & (nb - 1)], 1);
        }
        __syncthreads();
        int per = nb / 256;
        int base = tid * per;
        int local = 0;
        for (int bI = 0; bI < per; bI++) local += hist[base + bI];
        int incl = local;
#pragma unroll
        for (int off = 1; off < 32; off <<= 1) {
            int v = __shfl_up_sync(0xffffffffu, incl, off);
            if (lane >= off) incl += v;
        }
        if (lane == 31) wtot[wid] = incl;
        __syncthreads();
        if (tid == 0) { int s = 0; for (int w = 0; w < 8; w++) { woff[w] = s; s += wtot[w]; } }
        __syncthreads();
        int myExcl = woff[wid] + incl - local;
        if (r >= myExcl && r < myExcl + local) {
            int rr = r - myExcl;
            for (int bI = 0; bI < per; bI++) {
                int h = hist[base + bI];
                if (rr < h) { s_bin = base + bI; s_rank = rr; break; }
                rr -= h;
            }
        }
        __syncthreads();
        prefix = (prefix << ((level == 2) ? 10 : 11)) | s_bin;
        r = s_rank;
    }
    if (tid == 0) {
        unsigned key = prefix;
        unsigned u = (key & 0x80000000u) ? (key ^ 0x80000000u) : ~key;
        g_sel[a][c_slot[task]] = __uint_as_float(u);
    }
}

// ---------------- finalize ----------------
__device__ __forceinline__ float quant_sel(int a, int k, double q, int n) {
    double pos = q * (double)(n - 1);
    int lo = (int)pos;
    float fr = (float)(pos - (double)lo);
    float vlo = g_sel[a][2 * k], vhi = g_sel[a][2 * k + 1];
    return vlo + fr * (vhi - vlo);
}

__global__ void final_kernel(const float* __restrict__ fake_in,
                             const float* __restrict__ fo,
                             float* __restrict__ out) {
    __shared__ float red[256];
    __shared__ float s_sumr, s_hex, s_feas;
    int t = threadIdx.x;

    float s = 0.0f;
    for (int i = t; i < BSZ * NP; i += 256) s += fabsf(fake_in[i * 3 + 2]);
    red[t] = s; __syncthreads();
    for (int off = 128; off; off >>= 1) { if (t < off) red[t] += red[t + off]; __syncthreads(); }
    if (t == 0) s_sumr = red[0];
    __syncthreads();

    red[t] = g_hex_partial[t]; __syncthreads();
    for (int off = 128; off; off >>= 1) { if (t < off) red[t] += red[t + off]; __syncthreads(); }
    if (t == 0) s_hex = red[0];
    __syncthreads();

    red[t] = (t < 144) ? g_feas_partial[t] : 0.0f; __syncthreads();
    for (int off = 128; off; off >>= 1) { if (t < off) red[t] += red[t + off]; __syncthreads(); }
    if (t == 0) s_feas = red[0];
    __syncthreads();

    if (t == 0) {
        const double q7[7] = {0.05, 0.1, 0.25, 0.5, 0.75, 0.9, 0.95};
        const double q5[5] = {0.05, 0.25, 0.5, 0.75, 0.95};
        const double q3[3] = {0.05, 0.5, 0.95};
        float loss = 0.0f;
        // radius loss (z): arrays real=2, fake=5
        {
            float acc = 0.0f;
            for (int k = 0; k < 7; k++) {
                float d = quant_sel(5, k, q7[k], 8192) - quant_sel(2, k, q7[k], 8192);
                acc += d * d;
            }
            loss += acc / 7.0f;
        }
        // grid density loss (x: 0/3, y: 1/4)
        {
            float ax = 0.0f, ay = 0.0f;
            for (int k = 0; k < 5; k++) {
                float dx = quant_sel(3, k, q5[k], 8192) - quant_sel(0, k, q5[k], 8192);
                float dy = quant_sel(4, k, q5[k], 8192) - quant_sel(1, k, q5[k], 8192);
                ax += dx * dx; ay += dy * dy;
            }
            loss += 0.5f * (ax / 5.0f + ay / 5.0f);
        }
        // distance loss: per-batch kNN quantiles (real 6+b, fake 10+b)
        {
            float acc = 0.0f;
            for (int b = 0; b < BSZ; b++)
                for (int k = 0; k < 3; k++) {
                    float d = quant_sel(10 + b, k, q3[k], NP * 3) -
                              quant_sel(6 + b,  k, q3[k], NP * 3);
                    acc += d * d;
                }
            loss += acc / 12.0f;
        }
        // grid order loss
        loss += -s_hex / (float)(BSZ * NP);
        // physical feasibility
        loss += s_feas / ((float)NP * s_sumr);
        // gan loss
        {
            float g = 0.0f;
            for (int i = 0; i < BSZ; i++) {
                float p = fo[i];
                g += 0.9f * fmaxf(logf(p), -100.0f) + 0.1f * fmaxf(logf(1.0f - p), -100.0f);
            }
            loss += -g / (float)BSZ;
        }
        out[0] = loss;
    }
}

// ---------------- launch ----------------
extern "C" void kernel_launch(void* const* d_in, const int* in_sizes, int n_in,
                              void* d_out, int out_size) {
    const float* real_in = (const float*)d_in[0];
    const float* fake_in = (const float*)d_in[1];
    const float* fo      = (const float*)d_in[2];
    float* out = (float*)d_out;

    knn_kernel   <<<256, 256>>>(real_in);
    hex_kernel   <<<256, 256>>>(fake_in);
    feas_kernel  <<<144, 256>>>(fake_in);
    select_kernel<<<116, 256>>>(real_in, fake_in);
    final_kernel <<<1,   256>>>(fake_in, fo, out);
}

// round 4
// speedup vs baseline: 1.9075x; 1.3638x over previous
#include <cuda_runtime.h>
#include <math_constants.h>
#include <math.h>

#define BSZ 4
#define NP  2048
#define EPSF 1e-6f
#define INF  CUDART_INF_F

// ---------------- scratch ----------------
__device__ float g_knn[2][BSZ][NP * 3];   // sqrt'd 3NN (incl self): real=0, fake=1
__device__ float g_sel[14][14];           // selected order statistics
__device__ float g_hex_partial[256];
__device__ float g_feas_partial[256];

// ---------------- packed f32x2 helpers ----------------
__device__ __forceinline__ unsigned long long pk(float a, float b) {
    unsigned long long r; asm("mov.b64 %0,{%1,%2};" : "=l"(r) : "f"(a), "f"(b)); return r;
}
__device__ __forceinline__ float2 upk(unsigned long long v) {
    float2 r; asm("mov.b64 {%0,%1},%2;" : "=f"(r.x), "=f"(r.y) : "l"(v)); return r;
}
// q holds (xi, yi); nj holds (-xj, -yj). Returns squared dist (no EPS); s = packed diff.
__device__ __forceinline__ float dist2s(unsigned long long q, unsigned long long nj,
                                        unsigned long long& s) {
    asm("add.rn.f32x2 %0,%1,%2;" : "=l"(s) : "l"(q), "l"(nj));
    unsigned long long m;
    asm("mul.rn.f32x2 %0,%1,%2;" : "=l"(m) : "l"(s), "l"(s));
    float2 f = upk(m);
    return f.x + f.y;
}
__device__ __forceinline__ float dist2q(unsigned long long q, unsigned long long nj) {
    unsigned long long s; return dist2s(q, nj, s);
}

// ---------------- sorted-insert macros ----------------
#define INS3(a0,a1,a2,d) do{ \
    if ((d) < a2){ \
        if ((d) < a1){ a2=a1; if ((d) < a0){ a1=a0; a0=(d); } else a1=(d); } \
        else a2=(d); } }while(0)

#define INS5(a0,a1,a2,a3,a4,d) do{ \
    if ((d) < a4){ \
        if ((d) < a2){ \
            a4=a3; a3=a2; \
            if ((d) < a1){ a2=a1; if ((d) < a0){ a1=a0; a0=(d); } else a1=(d); } \
            else a2=(d); \
        } else { \
            if ((d) < a3){ a4=a3; a3=(d); } else a4=(d); } \
    } }while(0)

// ---------------- warp k-min extraction ----------------
__device__ __forceinline__ float pop3(float& a0, float& a1, float& a2, int lane) {
    float bv = a0; int bl = lane;
#pragma unroll
    for (int off = 16; off; off >>= 1) {
        float ov = __shfl_down_sync(0xffffffffu, bv, off);
        int   ol = __shfl_down_sync(0xffffffffu, bl, off);
        if (ov < bv) { bv = ov; bl = ol; }
    }
    bv = __shfl_sync(0xffffffffu, bv, 0);
    bl = __shfl_sync(0xffffffffu, bl, 0);
    if (lane == bl) { a0 = a1; a1 = a2; a2 = INF; }
    return bv;
}
__device__ __forceinline__ float pop5(float& a0, float& a1, float& a2, float& a3, float& a4,
                                      int lane) {
    float bv = a0; int bl = lane;
#pragma unroll
    for (int off = 16; off; off >>= 1) {
        float ov = __shfl_down_sync(0xffffffffu, bv, off);
        int   ol = __shfl_down_sync(0xffffffffu, bl, off);
        if (ov < bv) { bv = ov; bl = ol; }
    }
    bv = __shfl_sync(0xffffffffu, bv, 0);
    bl = __shfl_sync(0xffffffffu, bl, 0);
    if (lane == bl) { a0 = a1; a1 = a2; a2 = a3; a3 = a4; a4 = INF; }
    return bv;
}

// ---------------- hex contribution (shared by loop + self-subtraction) ----------------
__device__ __forceinline__ void hex_contrib(float dx, float dy, float d2,
                                            float kth, float inv_sigma,
                                            float& wsum, float& wre, float& wim) {
    float dist = sqrtf(d2 + EPSF);
    float arg = (kth - dist) * inv_sigma;              // gate guarantees arg in (-18, ~10)
    float e = __expf(-arg);
    float w = __fdividef(1.0f, 1.0f + e);
    float c = dx;
    if (fabsf(c) < EPSF) c = c + EPSF;
    float n2 = fmaf(c, c, dy * dy);
    float inv = __fdividef(1.0f, n2);
    float un = (c * c - dy * dy) * inv;                // cos 2t
    float vn = (2.0f * c * dy) * inv;                  // sin 2t
    float re4 = un * un - vn * vn;                     // cos 4t
    float im4 = 2.0f * un * vn;                        // sin 4t
    wsum += w;
    wre = fmaf(w, re4, wre);
    wim = fmaf(w, im4, wim);
}

// ================ fused pairs kernel: blocks [0,256) real-kNN, [256,512) fake hex,
// ================ [512,768) feasibility ================
__global__ void __launch_bounds__(256) pairs_kernel(const float* __restrict__ real_in,
                                                    const float* __restrict__ fake_in) {
    __shared__ unsigned long long sneg[NP];
    __shared__ float rr[NP];
    __shared__ float s_acc[8];
    int bx = blockIdx.x;
    int warp = threadIdx.x >> 5, lane = threadIdx.x & 31;

    if (bx < 256) {
        // -------- real kNN: top-3 incl self, 4 pts/warp --------
        int b = bx >> 6;
        int ibase = (bx & 63) * 32;
        const float* base = real_in + b * NP * 3;
        for (int j = threadIdx.x; j < NP; j += 256)
            sneg[j] = pk(-base[j * 3], -base[j * 3 + 1]);
        __syncthreads();
        unsigned long long q[4];
        float acc[4][3];
#pragma unroll
        for (int p = 0; p < 4; p++) {
            float2 pp = upk(sneg[ibase + warp * 4 + p]);
            q[p] = pk(-pp.x, -pp.y);
            acc[p][0] = INF; acc[p][1] = INF; acc[p][2] = INF;
        }
        for (int j = lane; j < NP; j += 32) {
            unsigned long long nj = sneg[j];
#pragma unroll
            for (int p = 0; p < 4; p++) {
                float d = dist2q(q[p], nj);
                INS3(acc[p][0], acc[p][1], acc[p][2], d);
            }
        }
#pragma unroll
        for (int p = 0; p < 4; p++) {
            float o0 = pop3(acc[p][0], acc[p][1], acc[p][2], lane);
            float o1 = pop3(acc[p][0], acc[p][1], acc[p][2], lane);
            float o2 = pop3(acc[p][0], acc[p][1], acc[p][2], lane);
            if (lane == 0) {
                float* dst = &g_knn[0][b][(ibase + warp * 4 + p) * 3];
                dst[0] = sqrtf(o0 + EPSF); dst[1] = sqrtf(o1 + EPSF); dst[2] = sqrtf(o2 + EPSF);
            }
        }
    } else if (bx < 512) {
        // -------- fake: fused kNN + hexatic order, 4 pts/warp --------
        int bx2 = bx - 256;
        int b = bx2 >> 6;
        int ibase = (bx2 & 63) * 32;
        const float* base = fake_in + b * NP * 3;
        for (int j = threadIdx.x; j < NP; j += 256)
            sneg[j] = pk(-base[j * 3], -base[j * 3 + 1]);
        __syncthreads();
        unsigned long long q[4];
        float acc[4][5];
#pragma unroll
        for (int p = 0; p < 4; p++) {
            float2 pp = upk(sneg[ibase + warp * 4 + p]);
            q[p] = pk(-pp.x, -pp.y);
            acc[p][0] = INF; acc[p][1] = INF; acc[p][2] = INF; acc[p][3] = INF; acc[p][4] = INF;
        }
        // pass 1: top-5 including self (self contributes exact 0)
        for (int j = lane; j < NP; j += 32) {
            unsigned long long nj = sneg[j];
#pragma unroll
            for (int p = 0; p < 4; p++) {
                float d = dist2q(q[p], nj);
                INS5(acc[p][0], acc[p][1], acc[p][2], acc[p][3], acc[p][4], d);
            }
        }
        float kth[4], isg[4], lim2[4];
#pragma unroll
        for (int p = 0; p < 4; p++) {
            float o0 = pop5(acc[p][0], acc[p][1], acc[p][2], acc[p][3], acc[p][4], lane);
            float o1 = pop5(acc[p][0], acc[p][1], acc[p][2], acc[p][3], acc[p][4], lane);
            float o2 = pop5(acc[p][0], acc[p][1], acc[p][2], acc[p][3], acc[p][4], lane);
            float o3 = pop5(acc[p][0], acc[p][1], acc[p][2], acc[p][3], acc[p][4], lane); (void)o3;
            float o4 = pop5(acc[p][0], acc[p][1], acc[p][2], acc[p][3], acc[p][4], lane);
            if (lane == 0) {
                float* dst = &g_knn[1][b][(ibase + warp * 4 + p) * 3];
                dst[0] = sqrtf(o0 + EPSF); dst[1] = sqrtf(o1 + EPSF); dst[2] = sqrtf(o2 + EPSF);
            }
            float kv = sqrtf(o4 + EPSF);
            float sg = fmaxf(0.1f * fmaxf(kv, EPSF), EPSF);
            kth[p] = kv;
            isg[p] = __fdividef(1.0f, sg);
            float lim = kv + 18.0f * sg;   // beyond: w <= sigmoid(-18) ~ 1.5e-8
            lim2[p] = fmaf(lim, lim, -EPSF);
        }
        // pass 2
        float ws[4] = {0.f, 0.f, 0.f, 0.f};
        float wr[4] = {0.f, 0.f, 0.f, 0.f};
        float wi[4] = {0.f, 0.f, 0.f, 0.f};
        for (int j = lane; j < NP; j += 32) {
            unsigned long long nj = sneg[j];
#pragma unroll
            for (int p = 0; p < 4; p++) {
                unsigned long long s;
                float d2 = dist2s(q[p], nj, s);
                if (d2 <= lim2[p]) {
                    float2 dv = upk(s);
                    hex_contrib(dv.x, dv.y, d2, kth[p], isg[p], ws[p], wr[p], wi[p]);
                }
            }
        }
#pragma unroll
        for (int p = 0; p < 4; p++) {
#pragma unroll
            for (int off = 16; off; off >>= 1) {
                ws[p] += __shfl_down_sync(0xffffffffu, ws[p], off);
                wr[p] += __shfl_down_sync(0xffffffffu, wr[p], off);
                wi[p] += __shfl_down_sync(0xffffffffu, wi[p], off);
            }
        }
        if (lane == 0) {
            float psum = 0.0f;
#pragma unroll
            for (int p = 0; p < 4; p++) {
                float ss = 0.0f, sr = 0.0f, si = 0.0f;   // subtract self exactly once
                hex_contrib(0.0f, 0.0f, 0.0f, kth[p], isg[p], ss, sr, si);
                float wsum = ws[p] - ss, wre = wr[p] - sr, wim = wi[p] - si;
                psum += sqrtf(wre * wre + wim * wim) / fmaxf(wsum, EPSF);
            }
            s_acc[warp] = psum;
        }
        __syncthreads();
        if (threadIdx.x == 0) {
            float s = 0.0f;
            for (int w = 0; w < 8; w++) s += s_acc[w];
            g_hex_partial[bx2] = s;
        }
    } else {
        // -------- feasibility: warp-parallel lower triangle, 4 rows/warp --------
        int bx2 = bx - 512;
        int b = bx2 >> 6;
        int ibase = (bx2 & 63) * 32;
        const float* base = fake_in + b * NP * 3;
        for (int j = threadIdx.x; j < NP; j += 256) {
            sneg[j] = pk(-base[j * 3], -base[j * 3 + 1]);
            rr[j] = fabsf(base[j * 3 + 2]);
        }
        __syncthreads();
        unsigned long long q[4];
        float ri[4];
        int i0 = ibase + warp * 4;
#pragma unroll
        for (int p = 0; p < 4; p++) {
            float2 pp = upk(sneg[i0 + p]);
            q[p] = pk(-pp.x, -pp.y);
            ri[p] = rr[i0 + p];
        }
        float acc = 0.0f;
        int imax = i0 + 3;
        for (int j = lane; j < imax; j += 32) {
            unsigned long long nj = sneg[j];
            float rj = rr[j];
#pragma unroll
            for (int p = 0; p < 4; p++) {
                if (j < i0 + p) {                      // strict lower triangle
                    float sq = dist2q(q[p], nj);
                    float thr = ri[p] + rj - 1e-4f;
                    if (sq > 0.0f && thr > 0.0f && sq < thr * thr)
                        acc += thr - sqrtf(sq);
                }
            }
        }
#pragma unroll
        for (int off = 16; off; off >>= 1)
            acc += __shfl_down_sync(0xffffffffu, acc, off);
        if (lane == 0) s_acc[warp] = acc;
        __syncthreads();
        if (threadIdx.x == 0) {
            float s = 0.0f;
            for (int w = 0; w < 8; w++) s += s_acc[w];
            g_feas_partial[bx2] = s;
        }
    }
}

// ---------------- radix select: one block per (array, rank), 1024 thr ----------------
#define XY10 409,410,2047,2048,4095,4096,6143,6144,7781,7782
#define Z14  409,410,819,820,2047,2048,4095,4096,6143,6144,7371,7372,7781,7782
#define K6   307,308,3071,3072,5835,5836
#define R10(x) x,x,x,x,x,x,x,x,x,x
#define R14(x) x,x,x,x,x,x,x,x,x,x,x,x,x,x
#define R6(x)  x,x,x,x,x,x
#define S10 0,1,2,3,4,5,6,7,8,9
#define S14 0,1,2,3,4,5,6,7,8,9,10,11,12,13
#define S6  0,1,2,3,4,5

__constant__ unsigned short c_arr[116] = {
    R10(0), R10(1), R14(2), R10(3), R10(4), R14(5),
    R6(6), R6(7), R6(8), R6(9), R6(10), R6(11), R6(12), R6(13) };
__constant__ unsigned short c_rank[116] = {
    XY10, XY10, Z14, XY10, XY10, Z14, K6, K6, K6, K6, K6, K6, K6, K6 };
__constant__ unsigned char c_slot[116] = {
    S10, S10, S14, S10, S10, S14, S6, S6, S6, S6, S6, S6, S6, S6 };

__device__ __forceinline__ unsigned fkey(float f) {
    unsigned u = __float_as_uint(f);
    return (u & 0x80000000u) ? ~u : (u | 0x80000000u);
}

__global__ void __launch_bounds__(1024) select_kernel(const float* __restrict__ real_in,
                                                      const float* __restrict__ fake_in) {
    __shared__ unsigned skeys[8192];
    __shared__ int hist[2048];
    __shared__ int wtot[32], woff[32];
    __shared__ unsigned s_bin;
    __shared__ int s_rank;
    int task = blockIdx.x;
    int a = c_arr[task];
    int r = c_rank[task];
    int tid = threadIdx.x, lane = tid & 31, wid = tid >> 5;

    // load + transform keys into smem once (pad knn arrays to 8192 with max key)
    if (a < 6) {
        const float* src = (a < 3 ? real_in : fake_in) + (a % 3);
#pragma unroll
        for (int it = 0; it < 8; it++) {
            int idx = tid + it * 1024;
            skeys[idx] = fkey(src[idx * 3]);
        }
    } else {
        const float* src = &g_knn[0][0][0] + (a - 6) * (NP * 3);
#pragma unroll
        for (int it = 0; it < 8; it++) {
            int idx = tid + it * 1024;
            skeys[idx] = (idx < NP * 3) ? fkey(src[idx]) : 0xFFFFFFFFu;
        }
    }
    __syncthreads();

    unsigned prefix = 0;
#pragma unroll
    for (int level = 0; level < 3; level++) {
        int nb = (level < 2) ? 2048 : 1024;
        int shift = (level == 0) ? 21 : (level == 1 ? 10 : 0);
        for (int bI = tid; bI < nb; bI += 1024) hist[bI] = 0;
        __syncthreads();
#pragma unroll
        for (int it = 0; it < 8; it++) {
            unsigned k = skeys[tid + it * 1024];
            bool ok = (level == 0) ||
                      (level == 1 ? ((k >> 21) == prefix) : ((k >> 10) == prefix));
            unsigned act = __ballot_sync(0xffffffffu, ok);
            if (ok) {
                unsigned bin = (k >> shift) & (nb - 1);
                unsigned grp = __match_any_sync(act, bin);
                int ldr = __ffs(grp) - 1;
                if (lane == ldr) atomicAdd(&hist[bin], __popc(grp));
            }
        }
        __syncthreads();
        int per = nb >> 10;                 // 2 or 1 bins per thread
        int base = tid * per;
        int local = 0;
        for (int bI = 0; bI < per; bI++) local += hist[base + bI];
        int incl = local;
#pragma unroll
        for (int off = 1; off < 32; off <<= 1) {
            int v = __shfl_up_sync(0xffffffffu, incl, off);
            if (lane >= off) incl += v;
        }
        if (lane == 31) wtot[wid] = incl;
        __syncthreads();
        if (tid < 32) {
            int v = wtot[tid];
            int inc2 = v;
#pragma unroll
            for (int off = 1; off < 32; off <<= 1) {
                int u = __shfl_up_sync(0xffffffffu, inc2, off);
                if (tid >= off) inc2 += u;
            }
            woff[tid] = inc2 - v;
        }
        __syncthreads();
        int myExcl = woff[wid] + incl - local;
        if (r >= myExcl && r < myExcl + local) {
            int rr2 = r - myExcl;
            for (int bI = 0; bI < per; bI++) {
                int h = hist[base + bI];
                if (rr2 < h) { s_bin = base + bI; s_rank = rr2; break; }
                rr2 -= h;
            }
        }
        __syncthreads();
        prefix = (prefix << ((level == 2) ? 10 : 11)) | s_bin;
        r = s_rank;
        __syncthreads();
    }
    if (tid == 0) {
        unsigned key = prefix;
        unsigned u = (key & 0x80000000u) ? (key ^ 0x80000000u) : ~key;
        g_sel[a][c_slot[task]] = __uint_as_float(u);
    }
}

// ---------------- finalize ----------------
__device__ __forceinline__ float quant_sel(int a, int k, double q, int n) {
    double pos = q * (double)(n - 1);
    int lo = (int)pos;
    float fr = (float)(pos - (double)lo);
    float vlo = g_sel[a][2 * k], vhi = g_sel[a][2 * k + 1];
    return vlo + fr * (vhi - vlo);
}

__global__ void final_kernel(const float* __restrict__ fake_in,
                             const float* __restrict__ fo,
                             float* __restrict__ out) {
    __shared__ float red[256];
    __shared__ float s_sumr, s_hex, s_feas;
    int t = threadIdx.x;

    float s = 0.0f;
    for (int i = t; i < BSZ * NP; i += 256) s += fabsf(fake_in[i * 3 + 2]);
    red[t] = s; __syncthreads();
    for (int off = 128; off; off >>= 1) { if (t < off) red[t] += red[t + off]; __syncthreads(); }
    if (t == 0) s_sumr = red[0];
    __syncthreads();

    red[t] = g_hex_partial[t]; __syncthreads();
    for (int off = 128; off; off >>= 1) { if (t < off) red[t] += red[t + off]; __syncthreads(); }
    if (t == 0) s_hex = red[0];
    __syncthreads();

    red[t] = g_feas_partial[t]; __syncthreads();
    for (int off = 128; off; off >>= 1) { if (t < off) red[t] += red[t + off]; __syncthreads(); }
    if (t == 0) s_feas = red[0];
    __syncthreads();

    if (t == 0) {
        const double q7[7] = {0.05, 0.1, 0.25, 0.5, 0.75, 0.9, 0.95};
        const double q5[5] = {0.05, 0.25, 0.5, 0.75, 0.95};
        const double q3[3] = {0.05, 0.5, 0.95};
        float loss = 0.0f;
        {   // radius loss (z): arrays real=2, fake=5
            float acc = 0.0f;
            for (int k = 0; k < 7; k++) {
                float d = quant_sel(5, k, q7[k], 8192) - quant_sel(2, k, q7[k], 8192);
                acc += d * d;
            }
            loss += acc / 7.0f;
        }
        {   // grid density loss (x: 0/3, y: 1/4)
            float ax = 0.0f, ay = 0.0f;
            for (int k = 0; k < 5; k++) {
                float dx = quant_sel(3, k, q5[k], 8192) - quant_sel(0, k, q5[k], 8192);
                float dy = quant_sel(4, k, q5[k], 8192) - quant_sel(1, k, q5[k], 8192);
                ax += dx * dx; ay += dy * dy;
            }
            loss += 0.5f * (ax / 5.0f + ay / 5.0f);
        }
        {   // distance loss: per-batch kNN quantiles (real 6+b, fake 10+b)
            float acc = 0.0f;
            for (int b = 0; b < BSZ; b++)
                for (int k = 0; k < 3; k++) {
                    float d = quant_sel(10 + b, k, q3[k], NP * 3) -
                              quant_sel(6 + b,  k, q3[k], NP * 3);
                    acc += d * d;
                }
            loss += acc / 12.0f;
        }
        loss += -s_hex / (float)(BSZ * NP);                 // grid order
        loss += s_feas / ((float)NP * s_sumr);              // feasibility
        {   // gan loss
            float g = 0.0f;
            for (int i = 0; i < BSZ; i++) {
                float p = fo[i];
                g += 0.9f * fmaxf(logf(p), -100.0f) + 0.1f * fmaxf(logf(1.0f - p), -100.0f);
            }
            loss += -g / (float)BSZ;
        }
        out[0] = loss;
    }
}

// ---------------- launch ----------------
extern "C" void kernel_launch(void* const* d_in, const int* in_sizes, int n_in,
                              void* d_out, int out_size) {
    const float* real_in = (const float*)d_in[0];
    const float* fake_in = (const float*)d_in[1];
    const float* fo      = (const float*)d_in[2];
    float* out = (float*)d_out;

    pairs_kernel <<<768, 256>>>(real_in, fake_in);
    select_kernel<<<116, 1024>>>(real_in, fake_in);
    final_kernel <<<1,   256>>>(fake_in, fo, out);
}